// round 16
// baseline (speedup 1.0000x reference)
#include <cuda_runtime.h>
#include <cuda_fp16.h>

#define N_NODES 100000
#define E_EDGES 1600000
#define INC 128
#define OUTC 64
#define LRELU_ALPHA 0.2f

#define SCAN_B 1024
#define SCAN_NBLK ((N_NODES + SCAN_B - 1) / SCAN_B)   // 98

// GEMM tiling
#define MBLK 64
#define GEMM_THREADS 128
#define XS 136

// Static device scratch (runtime allocation forbidden).
// g_hist is zero at module load; aggregate re-zeroes it at the end of
// every run, so the invariant holds across graph replays.
__device__ __align__(16) __half g_h[(size_t)N_NODES * OUTC];  // 12.8 MB (fp16)
__device__ float g_s[N_NODES];
__device__ float g_t[N_NODES];
__device__ float g_p[INC];
__device__ float g_q[INC];
__device__ int   g_hist[N_NODES];
__device__ int   g_start[N_NODES];
__device__ int   g_blocksum[SCAN_NBLK];
__device__ __align__(16) int2 g_sorted[E_EDGES];              // (dst, w) 12.8 MB
__device__ int   g_idx64;

// ---------------------------------------------------------------------------
// p = W @ a1, q = W @ a2 + index dtype detection.
// ---------------------------------------------------------------------------
__global__ __launch_bounds__(128) void pq_kernel(
    const float* __restrict__ W, const float* __restrict__ a,
    const int* __restrict__ ei32)
{
    __shared__ int nz;
    int k = threadIdx.x;
    if (k == 0) nz = 0;
    __syncthreads();
    if (k < 64 && __ldg(ei32 + 2 * k + 1) != 0) nz = 1;

    float p = 0.0f, q = 0.0f;
#pragma unroll 8
    for (int c = 0; c < OUTC; ++c) {
        float wv = __ldg(W + k * OUTC + c);
        p = fmaf(wv, __ldg(a + c), p);
        q = fmaf(wv, __ldg(a + OUTC + c), q);
    }
    g_p[k] = p;
    g_q[k] = q;
    __syncthreads();
    if (k == 0) g_idx64 = !nz;
}

// ---------------------------------------------------------------------------
// Warp-0 scan of the 98 block sums into smem (prologue helper).
// ---------------------------------------------------------------------------
__device__ __forceinline__ void blockoff_prologue(int* sboff, int tid)
{
    if (tid < 32) {
        int run = 0;
#pragma unroll
        for (int c = 0; c < (SCAN_NBLK + 31) / 32; ++c) {
            int idx = c * 32 + tid;
            int v = (idx < SCAN_NBLK) ? __ldg(g_blocksum + idx) : 0;
            int inc = v;
#pragma unroll
            for (int off = 1; off < 32; off <<= 1) {
                int n = __shfl_up_sync(0xFFFFFFFFu, inc, off);
                if (tid >= off) inc += n;
            }
            if (idx < SCAN_NBLK) sboff[idx] = run + inc - v;
            run += __shfl_sync(0xFFFFFFFFu, inc, 31);
        }
    }
    __syncthreads();
}

// ---------------------------------------------------------------------------
// h = x @ W via fp16 HMMA (fp32 accum); fused fp32 s,t (x.p / x.q).
// ---------------------------------------------------------------------------
__global__ __launch_bounds__(GEMM_THREADS) void gemm_kernel(
    const float* __restrict__ x, const float* __restrict__ W)
{
    __shared__ __align__(16) __half x_sh[MBLK * XS];
    __shared__ __align__(16) __half w_sh[OUTC * XS];

    int tid = threadIdx.x;
    int lane = tid & 31;
    int warp = tid >> 5;
    int rowbase = blockIdx.x * MBLK;

    {
        int n = tid & 63;
        int k0 = tid >> 6;
#pragma unroll 16
        for (int j = 0; j < 64; ++j) {
            int k = k0 + 2 * j;
            w_sh[n * XS + k] = __float2half_rn(__ldg(W + k * OUTC + n));
        }
    }

    {
        int r = tid >> 1;
        int hf = tid & 1;
        int grow = rowbase + r;
        float sp = 0.0f, tp = 0.0f;
        uint2* xsh2 = reinterpret_cast<uint2*>(x_sh);
        const float4* xr = reinterpret_cast<const float4*>(x) +
                           (size_t)grow * (INC / 4) + hf * 16;
        const float4* p4 = reinterpret_cast<const float4*>(g_p) + hf * 16;
        const float4* q4 = reinterpret_cast<const float4*>(g_q) + hf * 16;
        bool valid = grow < N_NODES;
#pragma unroll 4
        for (int i = 0; i < 16; ++i) {
            float4 xv = valid ? __ldg(xr + i) : make_float4(0.f, 0.f, 0.f, 0.f);
            float4 pv = __ldg(p4 + i);
            float4 qv = __ldg(q4 + i);
            sp = fmaf(xv.x, pv.x, sp); sp = fmaf(xv.y, pv.y, sp);
            sp = fmaf(xv.z, pv.z, sp); sp = fmaf(xv.w, pv.w, sp);
            tp = fmaf(xv.x, qv.x, tp); tp = fmaf(xv.y, qv.y, tp);
            tp = fmaf(xv.z, qv.z, tp); tp = fmaf(xv.w, qv.w, tp);
            __half2 h0 = __floats2half2_rn(xv.x, xv.y);
            __half2 h1 = __floats2half2_rn(xv.z, xv.w);
            uint2 u;
            u.x = *reinterpret_cast<unsigned*>(&h0);
            u.y = *reinterpret_cast<unsigned*>(&h1);
            xsh2[34 * r + 16 * hf + i] = u;
        }
        float s = sp + __shfl_xor_sync(0xFFFFFFFFu, sp, 1);
        float t = tp + __shfl_xor_sync(0xFFFFFFFFu, tp, 1);
        if (hf == 0 && valid) {
            g_s[grow] = s;
            g_t[grow] = t;
        }
    }
    __syncthreads();

    int g = lane >> 2;
    int t4 = lane & 3;
    const unsigned* xs32 = reinterpret_cast<const unsigned*>(x_sh);
    const unsigned* ws32 = reinterpret_cast<const unsigned*>(w_sh);

    float d[8][4];
#pragma unroll
    for (int nt = 0; nt < 8; ++nt)
#pragma unroll
        for (int i = 0; i < 4; ++i) d[nt][i] = 0.0f;

#pragma unroll
    for (int ks = 0; ks < 8; ++ks) {
        int r0 = warp * 16 + g;
        unsigned a0 = xs32[r0 * 68 + ks * 8 + t4];
        unsigned a1 = xs32[(r0 + 8) * 68 + ks * 8 + t4];
        unsigned a2 = xs32[r0 * 68 + ks * 8 + t4 + 4];
        unsigned a3 = xs32[(r0 + 8) * 68 + ks * 8 + t4 + 4];
#pragma unroll
        for (int nt = 0; nt < 8; ++nt) {
            int n = nt * 8 + g;
            unsigned b0 = ws32[n * 68 + ks * 8 + t4];
            unsigned b1 = ws32[n * 68 + ks * 8 + t4 + 4];
            asm volatile(
                "mma.sync.aligned.m16n8k16.row.col.f32.f16.f16.f32 "
                "{%0,%1,%2,%3},{%4,%5,%6,%7},{%8,%9},{%0,%1,%2,%3};"
                : "+f"(d[nt][0]), "+f"(d[nt][1]), "+f"(d[nt][2]), "+f"(d[nt][3])
                : "r"(a0), "r"(a1), "r"(a2), "r"(a3), "r"(b0), "r"(b1));
        }
    }

    __half2* gh2 = reinterpret_cast<__half2*>(g_h);
    int row0 = rowbase + warp * 16 + g;
    int row1 = row0 + 8;
#pragma unroll
    for (int nt = 0; nt < 8; ++nt) {
        if (row0 < N_NODES)
            gh2[(size_t)row0 * 32 + nt * 4 + t4] = __floats2half2_rn(d[nt][0], d[nt][1]);
        if (row1 < N_NODES)
            gh2[(size_t)row1 * 32 + nt * 4 + t4] = __floats2half2_rn(d[nt][2], d[nt][3]);
    }
}

// ---------------------------------------------------------------------------
__global__ __launch_bounds__(256) void hist_kernel(const void* __restrict__ ei)
{
    int q = blockIdx.x * blockDim.x + threadIdx.x;
    if (q >= E_EDGES / 4) return;
    int s0, s1, s2, s3;
    if (g_idx64) {
        const longlong2* p = (const longlong2*)ei;
        longlong2 a = __ldg(p + 2 * q);
        longlong2 b = __ldg(p + 2 * q + 1);
        s0 = (int)a.x; s1 = (int)a.y; s2 = (int)b.x; s3 = (int)b.y;
    } else {
        int4 v = __ldg((const int4*)ei + q);
        s0 = v.x; s1 = v.y; s2 = v.z; s3 = v.w;
    }
    atomicAdd(g_hist + s0, 1);
    atomicAdd(g_hist + s1, 1);
    atomicAdd(g_hist + s2, 1);
    atomicAdd(g_hist + s3, 1);
}

// ---------------------------------------------------------------------------
// scan1: per-block exclusive scan via warp shfl.
// ---------------------------------------------------------------------------
__global__ __launch_bounds__(SCAN_B) void scan1_kernel()
{
    __shared__ int wsum[32];
    int tid = threadIdx.x;
    int lane = tid & 31;
    int wid = tid >> 5;
    int i = blockIdx.x * SCAN_B + tid;
    int v = (i < N_NODES) ? g_hist[i] : 0;

    int inc = v;
#pragma unroll
    for (int off = 1; off < 32; off <<= 1) {
        int n = __shfl_up_sync(0xFFFFFFFFu, inc, off);
        if (lane >= off) inc += n;
    }
    if (lane == 31) wsum[wid] = inc;
    __syncthreads();
    if (wid == 0) {
        int w = wsum[lane];
        int wi = w;
#pragma unroll
        for (int off = 1; off < 32; off <<= 1) {
            int n = __shfl_up_sync(0xFFFFFFFFu, wi, off);
            if (lane >= off) wi += n;
        }
        wsum[lane] = wi - w;
    }
    __syncthreads();
    int excl = inc - v + wsum[wid];
    if (i < N_NODES) g_start[i] = excl;
    if (tid == SCAN_B - 1) g_blocksum[blockIdx.x] = excl + v;
}

// ---------------------------------------------------------------------------
// Scatter: computes w once, stores packed (dst,w); blockoff table computed
// in a per-block smem prologue (scan2 kernel eliminated).
// ---------------------------------------------------------------------------
__global__ __launch_bounds__(256) void scatter_kernel(const void* __restrict__ ei)
{
    __shared__ int sboff[SCAN_NBLK];
    blockoff_prologue(sboff, threadIdx.x);

    int q = blockIdx.x * blockDim.x + threadIdx.x;
    if (q >= E_EDGES / 2) return;
    int src0, src1, dst0, dst1;
    if (g_idx64) {
        const longlong2* p = (const longlong2*)ei;
        longlong2 sv = __ldg(p + q);
        longlong2 dv = __ldg(p + E_EDGES / 2 + q);
        src0 = (int)sv.x; src1 = (int)sv.y;
        dst0 = (int)dv.x; dst1 = (int)dv.y;
    } else {
        const int2* p = (const int2*)ei;
        int2 sv = __ldg(p + q);
        int2 dv = __ldg(p + E_EDGES / 2 + q);
        src0 = sv.x; src1 = sv.y;
        dst0 = dv.x; dst1 = dv.y;
    }

    float z0 = __ldg(g_s + src0) + __ldg(g_t + dst0);
    float z1 = __ldg(g_s + src1) + __ldg(g_t + dst1);
    float w0 = __expf((z0 > 0.0f) ? z0 : LRELU_ALPHA * z0);
    float w1 = __expf((z1 > 0.0f) ? z1 : LRELU_ALPHA * z1);

    int p0 = atomicAdd(g_start + src0, 1) + sboff[src0 >> 10];
    int p1 = atomicAdd(g_start + src1, 1) + sboff[src1 >> 10];
    g_sorted[p0] = make_int2(dst0, __float_as_int(w0));
    g_sorted[p1] = make_int2(dst1, __float_as_int(w1));
}

// ---------------------------------------------------------------------------
// Aggregate: 16 lanes per node; fp16 h gathers; fp32 accum; 2-edge unroll;
// blockoff via smem prologue; hist re-zeroed at the end.
// ---------------------------------------------------------------------------
__device__ __forceinline__ float4 h4_load(int nodeid, int sub) {
    uint2 u = __ldg(reinterpret_cast<const uint2*>(g_h + (size_t)nodeid * OUTC) + sub);
    __half2 p0 = *reinterpret_cast<__half2*>(&u.x);
    __half2 p1 = *reinterpret_cast<__half2*>(&u.y);
    float2 f0 = __half22float2(p0);
    float2 f1 = __half22float2(p1);
    return make_float4(f0.x, f0.y, f1.x, f1.y);
}

__global__ __launch_bounds__(256) void aggregate_kernel(float* __restrict__ out)
{
    __shared__ int sboff[SCAN_NBLK];
    blockoff_prologue(sboff, threadIdx.x);

    int gt = blockIdx.x * blockDim.x + threadIdx.x;
    int node = gt >> 4;
    int sub = gt & 15;
    if (node >= N_NODES) return;

    float z = __ldg(g_s + node) + __ldg(g_t + node);
    float wself = __expf((z > 0.0f) ? z : LRELU_ALPHA * z);

    float4 hv = h4_load(node, sub);
    float4 acc = make_float4(wself * hv.x, wself * hv.y, wself * hv.z, wself * hv.w);
    float es = wself;

    int cnt = __ldg(g_hist + node);
    int base = __ldg(g_start + node) + sboff[node >> 10] - cnt;

    int j = 0;
#pragma unroll 1
    for (; j + 2 <= cnt; j += 2) {
        int2 m0 = __ldg(g_sorted + base + j);
        int2 m1 = __ldg(g_sorted + base + j + 1);
        float4 v0 = h4_load(m0.x, sub);
        float4 v1 = h4_load(m1.x, sub);
        float w0 = __int_as_float(m0.y);
        float w1 = __int_as_float(m1.y);
        acc.x = fmaf(w0, v0.x, acc.x); acc.y = fmaf(w0, v0.y, acc.y);
        acc.z = fmaf(w0, v0.z, acc.z); acc.w = fmaf(w0, v0.w, acc.w);
        acc.x = fmaf(w1, v1.x, acc.x); acc.y = fmaf(w1, v1.y, acc.y);
        acc.z = fmaf(w1, v1.z, acc.z); acc.w = fmaf(w1, v1.w, acc.w);
        es += w0 + w1;
    }
    if (j < cnt) {
        int2 m0 = __ldg(g_sorted + base + j);
        float4 v0 = h4_load(m0.x, sub);
        float w0 = __int_as_float(m0.y);
        acc.x = fmaf(w0, v0.x, acc.x); acc.y = fmaf(w0, v0.y, acc.y);
        acc.z = fmaf(w0, v0.z, acc.z); acc.w = fmaf(w0, v0.w, acc.w);
        es += w0;
    }

    float inv = 1.0f / es;
    reinterpret_cast<float4*>(out)[(size_t)node * 16 + sub] =
        make_float4(acc.x * inv, acc.y * inv, acc.z * inv, acc.w * inv);

    if (sub == 0) g_hist[node] = 0;   // invariant for the next replay
}

// ---------------------------------------------------------------------------
// Topology: pq -> fork { side: hist -> scan1 -> scatter } ∥ { gemm }
//           -> join -> aggregate         (6 launches total)
// ---------------------------------------------------------------------------
extern "C" void kernel_launch(void* const* d_in, const int* in_sizes, int n_in,
                              void* d_out, int out_size)
{
    const float* x = (const float*)d_in[0];
    const float* W = (const float*)d_in[1];
    const float* a = (const float*)d_in[2];
    const void*  ei = d_in[3];
    float* out = (float*)d_out;

    static cudaStream_t side = nullptr;
    static cudaEvent_t evFork = nullptr, evJoin = nullptr;
    if (side == nullptr) {
        cudaStreamCreateWithFlags(&side, cudaStreamNonBlocking);
        cudaEventCreateWithFlags(&evFork, cudaEventDisableTiming);
        cudaEventCreateWithFlags(&evJoin, cudaEventDisableTiming);
    }

    pq_kernel<<<1, 128>>>(W, a, (const int*)ei);
    cudaEventRecord(evFork, 0);
    cudaStreamWaitEvent(side, evFork, 0);

    // index chain (feeds aggregate via g_sorted)
    hist_kernel<<<(E_EDGES / 4 + 255) / 256, 256, 0, side>>>(ei);
    scan1_kernel<<<SCAN_NBLK, SCAN_B, 0, side>>>();
    scatter_kernel<<<(E_EDGES / 2 + 255) / 256, 256, 0, side>>>(ei);
    cudaEventRecord(evJoin, side);

    // feature chain
    gemm_kernel<<<(N_NODES + MBLK - 1) / MBLK, GEMM_THREADS>>>(x, W);

    cudaStreamWaitEvent(0, evJoin, 0);
    aggregate_kernel<<<(N_NODES * 16 + 255) / 256, 256>>>(out);
}

// round 17
// speedup vs baseline: 1.1070x; 1.1070x over previous
#include <cuda_runtime.h>
#include <cuda_fp16.h>

#define N_NODES 100000
#define E_EDGES 1600000
#define INC 128
#define OUTC 64
#define LRELU_ALPHA 0.2f

#define SCAN_B 1024
#define SCAN_NBLK ((N_NODES + SCAN_B - 1) / SCAN_B)   // 98

// GEMM tiling
#define MBLK 64
#define GEMM_THREADS 128
#define XS 136

// Static device scratch (runtime allocation forbidden).
// g_hist is zero at module load; aggregate re-zeroes it at the end of
// every run, so the invariant holds across graph replays.
__device__ __align__(16) __half g_h[(size_t)N_NODES * OUTC];  // 12.8 MB (fp16)
__device__ float g_s[N_NODES];
__device__ float g_t[N_NODES];
__device__ float g_p[INC];
__device__ float g_q[INC];
__device__ int   g_hist[N_NODES];
__device__ int   g_start[N_NODES];
__device__ int   g_blocksum[SCAN_NBLK];
__device__ int   g_blockoff[SCAN_NBLK];
__device__ __align__(16) int2 g_sorted[E_EDGES];              // (dst, w) 12.8 MB
__device__ int   g_idx64;

// ---------------------------------------------------------------------------
// p = W @ a1, q = W @ a2 + index dtype detection.
// ---------------------------------------------------------------------------
__global__ __launch_bounds__(128) void pq_kernel(
    const float* __restrict__ W, const float* __restrict__ a,
    const int* __restrict__ ei32)
{
    __shared__ int nz;
    int k = threadIdx.x;
    if (k == 0) nz = 0;
    __syncthreads();
    if (k < 64 && __ldg(ei32 + 2 * k + 1) != 0) nz = 1;

    float p = 0.0f, q = 0.0f;
#pragma unroll 8
    for (int c = 0; c < OUTC; ++c) {
        float wv = __ldg(W + k * OUTC + c);
        p = fmaf(wv, __ldg(a + c), p);
        q = fmaf(wv, __ldg(a + OUTC + c), q);
    }
    g_p[k] = p;
    g_q[k] = q;
    __syncthreads();
    if (k == 0) g_idx64 = !nz;
}

// ---------------------------------------------------------------------------
// h = x @ W via fp16 HMMA (fp32 accum); fused fp32 s,t (x.p / x.q).
// ---------------------------------------------------------------------------
__global__ __launch_bounds__(GEMM_THREADS) void gemm_kernel(
    const float* __restrict__ x, const float* __restrict__ W)
{
    __shared__ __align__(16) __half x_sh[MBLK * XS];
    __shared__ __align__(16) __half w_sh[OUTC * XS];

    int tid = threadIdx.x;
    int lane = tid & 31;
    int warp = tid >> 5;
    int rowbase = blockIdx.x * MBLK;

    {
        int n = tid & 63;
        int k0 = tid >> 6;
#pragma unroll 16
        for (int j = 0; j < 64; ++j) {
            int k = k0 + 2 * j;
            w_sh[n * XS + k] = __float2half_rn(__ldg(W + k * OUTC + n));
        }
    }

    {
        int r = tid >> 1;
        int hf = tid & 1;
        int grow = rowbase + r;
        float sp = 0.0f, tp = 0.0f;
        uint2* xsh2 = reinterpret_cast<uint2*>(x_sh);
        const float4* xr = reinterpret_cast<const float4*>(x) +
                           (size_t)grow * (INC / 4) + hf * 16;
        const float4* p4 = reinterpret_cast<const float4*>(g_p) + hf * 16;
        const float4* q4 = reinterpret_cast<const float4*>(g_q) + hf * 16;
        bool valid = grow < N_NODES;
#pragma unroll 4
        for (int i = 0; i < 16; ++i) {
            float4 xv = valid ? __ldg(xr + i) : make_float4(0.f, 0.f, 0.f, 0.f);
            float4 pv = __ldg(p4 + i);
            float4 qv = __ldg(q4 + i);
            sp = fmaf(xv.x, pv.x, sp); sp = fmaf(xv.y, pv.y, sp);
            sp = fmaf(xv.z, pv.z, sp); sp = fmaf(xv.w, pv.w, sp);
            tp = fmaf(xv.x, qv.x, tp); tp = fmaf(xv.y, qv.y, tp);
            tp = fmaf(xv.z, qv.z, tp); tp = fmaf(xv.w, qv.w, tp);
            __half2 h0 = __floats2half2_rn(xv.x, xv.y);
            __half2 h1 = __floats2half2_rn(xv.z, xv.w);
            uint2 u;
            u.x = *reinterpret_cast<unsigned*>(&h0);
            u.y = *reinterpret_cast<unsigned*>(&h1);
            xsh2[34 * r + 16 * hf + i] = u;
        }
        float s = sp + __shfl_xor_sync(0xFFFFFFFFu, sp, 1);
        float t = tp + __shfl_xor_sync(0xFFFFFFFFu, tp, 1);
        if (hf == 0 && valid) {
            g_s[grow] = s;
            g_t[grow] = t;
        }
    }
    __syncthreads();

    int g = lane >> 2;
    int t4 = lane & 3;
    const unsigned* xs32 = reinterpret_cast<const unsigned*>(x_sh);
    const unsigned* ws32 = reinterpret_cast<const unsigned*>(w_sh);

    float d[8][4];
#pragma unroll
    for (int nt = 0; nt < 8; ++nt)
#pragma unroll
        for (int i = 0; i < 4; ++i) d[nt][i] = 0.0f;

#pragma unroll
    for (int ks = 0; ks < 8; ++ks) {
        int r0 = warp * 16 + g;
        unsigned a0 = xs32[r0 * 68 + ks * 8 + t4];
        unsigned a1 = xs32[(r0 + 8) * 68 + ks * 8 + t4];
        unsigned a2 = xs32[r0 * 68 + ks * 8 + t4 + 4];
        unsigned a3 = xs32[(r0 + 8) * 68 + ks * 8 + t4 + 4];
#pragma unroll
        for (int nt = 0; nt < 8; ++nt) {
            int n = nt * 8 + g;
            unsigned b0 = ws32[n * 68 + ks * 8 + t4];
            unsigned b1 = ws32[n * 68 + ks * 8 + t4 + 4];
            asm volatile(
                "mma.sync.aligned.m16n8k16.row.col.f32.f16.f16.f32 "
                "{%0,%1,%2,%3},{%4,%5,%6,%7},{%8,%9},{%0,%1,%2,%3};"
                : "+f"(d[nt][0]), "+f"(d[nt][1]), "+f"(d[nt][2]), "+f"(d[nt][3])
                : "r"(a0), "r"(a1), "r"(a2), "r"(a3), "r"(b0), "r"(b1));
        }
    }

    __half2* gh2 = reinterpret_cast<__half2*>(g_h);
    int row0 = rowbase + warp * 16 + g;
    int row1 = row0 + 8;
#pragma unroll
    for (int nt = 0; nt < 8; ++nt) {
        if (row0 < N_NODES)
            gh2[(size_t)row0 * 32 + nt * 4 + t4] = __floats2half2_rn(d[nt][0], d[nt][1]);
        if (row1 < N_NODES)
            gh2[(size_t)row1 * 32 + nt * 4 + t4] = __floats2half2_rn(d[nt][2], d[nt][3]);
    }
}

// ---------------------------------------------------------------------------
__global__ __launch_bounds__(256) void hist_kernel(const void* __restrict__ ei)
{
    int q = blockIdx.x * blockDim.x + threadIdx.x;
    if (q >= E_EDGES / 4) return;
    int s0, s1, s2, s3;
    if (g_idx64) {
        const longlong2* p = (const longlong2*)ei;
        longlong2 a = __ldg(p + 2 * q);
        longlong2 b = __ldg(p + 2 * q + 1);
        s0 = (int)a.x; s1 = (int)a.y; s2 = (int)b.x; s3 = (int)b.y;
    } else {
        int4 v = __ldg((const int4*)ei + q);
        s0 = v.x; s1 = v.y; s2 = v.z; s3 = v.w;
    }
    atomicAdd(g_hist + s0, 1);
    atomicAdd(g_hist + s1, 1);
    atomicAdd(g_hist + s2, 1);
    atomicAdd(g_hist + s3, 1);
}

// ---------------------------------------------------------------------------
// scan1: per-block exclusive scan via warp shfl.
// ---------------------------------------------------------------------------
__global__ __launch_bounds__(SCAN_B) void scan1_kernel()
{
    __shared__ int wsum[32];
    int tid = threadIdx.x;
    int lane = tid & 31;
    int wid = tid >> 5;
    int i = blockIdx.x * SCAN_B + tid;
    int v = (i < N_NODES) ? g_hist[i] : 0;

    int inc = v;
#pragma unroll
    for (int off = 1; off < 32; off <<= 1) {
        int n = __shfl_up_sync(0xFFFFFFFFu, inc, off);
        if (lane >= off) inc += n;
    }
    if (lane == 31) wsum[wid] = inc;
    __syncthreads();
    if (wid == 0) {
        int w = wsum[lane];
        int wi = w;
#pragma unroll
        for (int off = 1; off < 32; off <<= 1) {
            int n = __shfl_up_sync(0xFFFFFFFFu, wi, off);
            if (lane >= off) wi += n;
        }
        wsum[lane] = wi - w;
    }
    __syncthreads();
    int excl = inc - v + wsum[wid];
    if (i < N_NODES) g_start[i] = excl;
    if (tid == SCAN_B - 1) g_blocksum[blockIdx.x] = excl + v;
}

// ---------------------------------------------------------------------------
// scan2: scan 98 block sums, one block of 128 threads, shfl scan.
// ---------------------------------------------------------------------------
__global__ __launch_bounds__(128) void scan2_kernel()
{
    __shared__ int warpsum[4];
    int tid = threadIdx.x;
    int lane = tid & 31;
    int wid = tid >> 5;

    int v = (tid < SCAN_NBLK) ? g_blocksum[tid] : 0;
    int inc = v;
#pragma unroll
    for (int off = 1; off < 32; off <<= 1) {
        int n = __shfl_up_sync(0xFFFFFFFFu, inc, off);
        if (lane >= off) inc += n;
    }
    if (lane == 31) warpsum[wid] = inc;
    __syncthreads();
    if (wid == 0 && lane < 4) {
        int ws = warpsum[lane];
        int wi = ws;
#pragma unroll
        for (int off = 1; off < 4; off <<= 1) {
            int n = __shfl_up_sync(0xFu, wi, off);
            if (lane >= off) wi += n;
        }
        warpsum[lane] = wi - ws;
    }
    __syncthreads();
    if (tid < SCAN_NBLK)
        g_blockoff[tid] = inc - v + warpsum[wid];
}

// ---------------------------------------------------------------------------
// Scatter: computes w once, stores packed (dst,w). Runs on the main stream
// after the join (not concurrent with gemm -- L2 contention hurt in R16).
// ---------------------------------------------------------------------------
__global__ __launch_bounds__(256) void scatter_kernel(const void* __restrict__ ei)
{
    int q = blockIdx.x * blockDim.x + threadIdx.x;
    if (q >= E_EDGES / 2) return;
    int src0, src1, dst0, dst1;
    if (g_idx64) {
        const longlong2* p = (const longlong2*)ei;
        longlong2 sv = __ldg(p + q);
        longlong2 dv = __ldg(p + E_EDGES / 2 + q);
        src0 = (int)sv.x; src1 = (int)sv.y;
        dst0 = (int)dv.x; dst1 = (int)dv.y;
    } else {
        const int2* p = (const int2*)ei;
        int2 sv = __ldg(p + q);
        int2 dv = __ldg(p + E_EDGES / 2 + q);
        src0 = sv.x; src1 = sv.y;
        dst0 = dv.x; dst1 = dv.y;
    }

    float z0 = __ldg(g_s + src0) + __ldg(g_t + dst0);
    float z1 = __ldg(g_s + src1) + __ldg(g_t + dst1);
    float w0 = __expf((z0 > 0.0f) ? z0 : LRELU_ALPHA * z0);
    float w1 = __expf((z1 > 0.0f) ? z1 : LRELU_ALPHA * z1);

    int p0 = atomicAdd(g_start + src0, 1) + __ldg(g_blockoff + (src0 >> 10));
    int p1 = atomicAdd(g_start + src1, 1) + __ldg(g_blockoff + (src1 >> 10));
    g_sorted[p0] = make_int2(dst0, __float_as_int(w0));
    g_sorted[p1] = make_int2(dst1, __float_as_int(w1));
}

// ---------------------------------------------------------------------------
// Aggregate: 16 lanes per node; fp16 h gathers; fp32 accum; 2-edge unroll;
// hist re-zeroed at the end (replay invariant).
// ---------------------------------------------------------------------------
__device__ __forceinline__ float4 h4_load(int nodeid, int sub) {
    uint2 u = __ldg(reinterpret_cast<const uint2*>(g_h + (size_t)nodeid * OUTC) + sub);
    __half2 p0 = *reinterpret_cast<__half2*>(&u.x);
    __half2 p1 = *reinterpret_cast<__half2*>(&u.y);
    float2 f0 = __half22float2(p0);
    float2 f1 = __half22float2(p1);
    return make_float4(f0.x, f0.y, f1.x, f1.y);
}

__global__ __launch_bounds__(256) void aggregate_kernel(float* __restrict__ out)
{
    int gt = blockIdx.x * blockDim.x + threadIdx.x;
    int node = gt >> 4;
    int sub = gt & 15;
    if (node >= N_NODES) return;

    float z = __ldg(g_s + node) + __ldg(g_t + node);
    float wself = __expf((z > 0.0f) ? z : LRELU_ALPHA * z);

    float4 hv = h4_load(node, sub);
    float4 acc = make_float4(wself * hv.x, wself * hv.y, wself * hv.z, wself * hv.w);
    float es = wself;

    int cnt = __ldg(g_hist + node);
    int base = __ldg(g_start + node) + __ldg(g_blockoff + (node >> 10)) - cnt;

    int j = 0;
#pragma unroll 1
    for (; j + 2 <= cnt; j += 2) {
        int2 m0 = __ldg(g_sorted + base + j);
        int2 m1 = __ldg(g_sorted + base + j + 1);
        float4 v0 = h4_load(m0.x, sub);
        float4 v1 = h4_load(m1.x, sub);
        float w0 = __int_as_float(m0.y);
        float w1 = __int_as_float(m1.y);
        acc.x = fmaf(w0, v0.x, acc.x); acc.y = fmaf(w0, v0.y, acc.y);
        acc.z = fmaf(w0, v0.z, acc.z); acc.w = fmaf(w0, v0.w, acc.w);
        acc.x = fmaf(w1, v1.x, acc.x); acc.y = fmaf(w1, v1.y, acc.y);
        acc.z = fmaf(w1, v1.z, acc.z); acc.w = fmaf(w1, v1.w, acc.w);
        es += w0 + w1;
    }
    if (j < cnt) {
        int2 m0 = __ldg(g_sorted + base + j);
        float4 v0 = h4_load(m0.x, sub);
        float w0 = __int_as_float(m0.y);
        acc.x = fmaf(w0, v0.x, acc.x); acc.y = fmaf(w0, v0.y, acc.y);
        acc.z = fmaf(w0, v0.z, acc.z); acc.w = fmaf(w0, v0.w, acc.w);
        es += w0;
    }

    float inv = 1.0f / es;
    reinterpret_cast<float4*>(out)[(size_t)node * 16 + sub] =
        make_float4(acc.x * inv, acc.y * inv, acc.z * inv, acc.w * inv);

    if (sub == 0) g_hist[node] = 0;   // invariant for the next replay
}

// ---------------------------------------------------------------------------
// Topology: pq -> fork { side: hist -> scan1 -> scan2 } ∥ { gemm }
//           -> join -> scatter -> aggregate       (7 launches)
// ---------------------------------------------------------------------------
extern "C" void kernel_launch(void* const* d_in, const int* in_sizes, int n_in,
                              void* d_out, int out_size)
{
    const float* x = (const float*)d_in[0];
    const float* W = (const float*)d_in[1];
    const float* a = (const float*)d_in[2];
    const void*  ei = d_in[3];
    float* out = (float*)d_out;

    static cudaStream_t side = nullptr;
    static cudaEvent_t evFork = nullptr, evJoin = nullptr;
    if (side == nullptr) {
        cudaStreamCreateWithFlags(&side, cudaStreamNonBlocking);
        cudaEventCreateWithFlags(&evFork, cudaEventDisableTiming);
        cudaEventCreateWithFlags(&evJoin, cudaEventDisableTiming);
    }

    pq_kernel<<<1, 128>>>(W, a, (const int*)ei);
    cudaEventRecord(evFork, 0);
    cudaStreamWaitEvent(side, evFork, 0);

    // index chain
    hist_kernel<<<(E_EDGES / 4 + 255) / 256, 256, 0, side>>>(ei);
    scan1_kernel<<<SCAN_NBLK, SCAN_B, 0, side>>>();
    scan2_kernel<<<1, 128, 0, side>>>();
    cudaEventRecord(evJoin, side);

    // feature chain
    gemm_kernel<<<(N_NODES + MBLK - 1) / MBLK, GEMM_THREADS>>>(x, W);

    cudaStreamWaitEvent(0, evJoin, 0);
    scatter_kernel<<<(E_EDGES / 2 + 255) / 256, 256>>>(ei);
    aggregate_kernel<<<(N_NODES * 16 + 255) / 256, 256>>>(out);
}